// round 3
// baseline (speedup 1.0000x reference)
#include <cuda_runtime.h>

#define N_ROWS 32768
#define K_ANCH 32
#define D_FEAT 128

// Precomputed xw = x @ w for both branches (allocation-free scratch).
__device__ float g_xw[2][N_ROWS];

// xw[n] = dot(x[n,:], w[0,:]). Warp per row, float4 lanes. gridDim.y = branch.
__global__ __launch_bounds__(256) void xw_kernel(const float* __restrict__ x1,
                                                 const float* __restrict__ x2,
                                                 const float* __restrict__ w) {
    int br   = blockIdx.y;
    const float* x = br ? x2 : x1;
    int warp = threadIdx.x >> 5;
    int lane = threadIdx.x & 31;
    int row  = blockIdx.x * 8 + warp;

    float4 xv = reinterpret_cast<const float4*>(x)[row * (D_FEAT / 4) + lane];
    float4 wv = reinterpret_cast<const float4*>(w)[lane];
    float s = xv.x * wv.x + xv.y * wv.y + xv.z * wv.z + xv.w * wv.w;
    #pragma unroll
    for (int off = 16; off > 0; off >>= 1)
        s += __shfl_xor_sync(0xFFFFFFFFu, s, off);
    if (lane == 0) g_xw[br][row] = s;
}

// Fused gather for both branches. Warp per row, float4 per lane.
// Software-pipelined with an 8-deep register stage so ~8 LDG.128 per thread
// are outstanding (covers L2 ~250cyc latency at high L2 utilization).
__global__ __launch_bounds__(256, 4) void fused_gather_kernel(
    const float* __restrict__ x1, const int* __restrict__ idx1, const float* __restrict__ dm1,
    const float* __restrict__ x2, const int* __restrict__ idx2, const float* __restrict__ dm2,
    const float* __restrict__ b_out,
    float* __restrict__ op1, float* __restrict__ os1,
    float* __restrict__ op2, float* __restrict__ os2)
{
    const int br = blockIdx.y;
    const float* __restrict__ x   = br ? x2   : x1;
    const int*   __restrict__ idx = br ? idx2 : idx1;
    const float* __restrict__ dm  = br ? dm2  : dm1;
    float*       __restrict__ op  = br ? op2  : op1;
    float*       __restrict__ os  = br ? os2  : os1;
    const float* __restrict__ xw  = g_xw[br];

    const int warp = threadIdx.x >> 5;
    const int lane = threadIdx.x & 31;
    const int n    = blockIdx.x * 8 + warp;

    // Per-warp staging: packed (byte_offset, dmax_bits) per k.
    __shared__ int2 s_kd[8][K_ANCH];

    const int   a = idx[n * K_ANCH + lane];     // coalesced
    const float d = dm [n * K_ANCH + lane];     // coalesced
    s_kd[warp][lane] = make_int2(a * (int)(D_FEAT * sizeof(float)), __float_as_int(d));
    __syncwarp();

    // op for this lane's k (4B gather from the 128KB xw table — L1-friendly).
    const float opv = d * __ldg(&xw[a]) + b_out[0];

    const char* __restrict__ xb = reinterpret_cast<const char*>(x);
    const int lane_byte = lane * 16;

    // ---- software pipeline: stage depth 8 ----
    float4 buf[8];
    float  dk [8];
    #pragma unroll
    for (int i = 0; i < 8; i++) {
        int2 kd = s_kd[warp][i];
        dk[i]  = __int_as_float(kd.y);
        buf[i] = __ldg(reinterpret_cast<const float4*>(xb + kd.x + lane_byte));
    }

    float4 acc0 = make_float4(0.f, 0.f, 0.f, 0.f);
    float4 acc1 = make_float4(0.f, 0.f, 0.f, 0.f);
    float4 acc2 = make_float4(0.f, 0.f, 0.f, 0.f);
    float4 acc3 = make_float4(0.f, 0.f, 0.f, 0.f);

    #pragma unroll
    for (int g = 0; g < 3; g++) {           // groups 1..3: consume stage g, load g+1
        float4 nbuf[8];
        float  ndk [8];
        #pragma unroll
        for (int i = 0; i < 8; i++) {
            int2 kd = s_kd[warp][(g + 1) * 8 + i];
            ndk[i]  = __int_as_float(kd.y);
            nbuf[i] = __ldg(reinterpret_cast<const float4*>(xb + kd.x + lane_byte));
        }
        #pragma unroll
        for (int i = 0; i < 8; i += 4) {
            acc0.x += dk[i+0] * buf[i+0].x; acc0.y += dk[i+0] * buf[i+0].y;
            acc0.z += dk[i+0] * buf[i+0].z; acc0.w += dk[i+0] * buf[i+0].w;
            acc1.x += dk[i+1] * buf[i+1].x; acc1.y += dk[i+1] * buf[i+1].y;
            acc1.z += dk[i+1] * buf[i+1].z; acc1.w += dk[i+1] * buf[i+1].w;
            acc2.x += dk[i+2] * buf[i+2].x; acc2.y += dk[i+2] * buf[i+2].y;
            acc2.z += dk[i+2] * buf[i+2].z; acc2.w += dk[i+2] * buf[i+2].w;
            acc3.x += dk[i+3] * buf[i+3].x; acc3.y += dk[i+3] * buf[i+3].y;
            acc3.z += dk[i+3] * buf[i+3].z; acc3.w += dk[i+3] * buf[i+3].w;
        }
        #pragma unroll
        for (int i = 0; i < 8; i++) { buf[i] = nbuf[i]; dk[i] = ndk[i]; }
    }
    // drain last stage
    #pragma unroll
    for (int i = 0; i < 8; i += 4) {
        acc0.x += dk[i+0] * buf[i+0].x; acc0.y += dk[i+0] * buf[i+0].y;
        acc0.z += dk[i+0] * buf[i+0].z; acc0.w += dk[i+0] * buf[i+0].w;
        acc1.x += dk[i+1] * buf[i+1].x; acc1.y += dk[i+1] * buf[i+1].y;
        acc1.z += dk[i+1] * buf[i+1].z; acc1.w += dk[i+1] * buf[i+1].w;
        acc2.x += dk[i+2] * buf[i+2].x; acc2.y += dk[i+2] * buf[i+2].y;
        acc2.z += dk[i+2] * buf[i+2].z; acc2.w += dk[i+2] * buf[i+2].w;
        acc3.x += dk[i+3] * buf[i+3].x; acc3.y += dk[i+3] * buf[i+3].y;
        acc3.z += dk[i+3] * buf[i+3].z; acc3.w += dk[i+3] * buf[i+3].w;
    }

    const float inv = 1.0f / (float)K_ANCH;
    float4 acc;
    acc.x = (acc0.x + acc1.x + acc2.x + acc3.x) * inv;
    acc.y = (acc0.y + acc1.y + acc2.y + acc3.y) * inv;
    acc.z = (acc0.z + acc1.z + acc2.z + acc3.z) * inv;
    acc.w = (acc0.w + acc1.w + acc2.w + acc3.w) * inv;

    reinterpret_cast<float4*>(os)[n * (D_FEAT / 4) + lane] = acc;   // coalesced
    op[n * K_ANCH + lane] = opv;                                    // coalesced
}

extern "C" void kernel_launch(void* const* d_in, const int* in_sizes, int n_in,
                              void* d_out, int out_size) {
    const float* x1   = (const float*)d_in[0];
    const int*   idx1 = (const int*)  d_in[1];
    const float* dm1  = (const float*)d_in[2];
    const float* x2   = (const float*)d_in[3];
    const int*   idx2 = (const int*)  d_in[4];
    const float* dm2  = (const float*)d_in[5];
    const float* w    = (const float*)d_in[6];
    const float* b    = (const float*)d_in[7];

    float* out = (float*)d_out;
    float* op1 = out;                                       // [N, K]
    float* os1 = op1 + (size_t)N_ROWS * K_ANCH;             // [N, D]
    float* op2 = os1 + (size_t)N_ROWS * D_FEAT;             // [N, K]
    float* os2 = op2 + (size_t)N_ROWS * K_ANCH;             // [N, D]

    dim3 xg(N_ROWS / 8, 2);
    xw_kernel<<<xg, 256>>>(x1, x2, w);

    dim3 gg(N_ROWS / 8, 2);
    fused_gather_kernel<<<gg, 256>>>(x1, idx1, dm1, x2, idx2, dm2, b,
                                     op1, os1, op2, os2);
}

// round 4
// speedup vs baseline: 1.0381x; 1.0381x over previous
#include <cuda_runtime.h>

#define N_ROWS 32768
#define K_ANCH 32
#define D_FEAT 128

// Precomputed xw = x @ w for both branches (allocation-free scratch).
__device__ float g_xw[2][N_ROWS];

// xw[n] = dot(x[n,:], w[0,:]). Warp per row, float4 lanes. gridDim.y = branch.
__global__ __launch_bounds__(256) void xw_kernel(const float* __restrict__ x1,
                                                 const float* __restrict__ x2,
                                                 const float* __restrict__ w) {
    int br   = blockIdx.y;
    const float* x = br ? x2 : x1;
    int warp = threadIdx.x >> 5;
    int lane = threadIdx.x & 31;
    int row  = blockIdx.x * 8 + warp;

    float4 xv = reinterpret_cast<const float4*>(x)[row * (D_FEAT / 4) + lane];
    float4 wv = reinterpret_cast<const float4*>(w)[lane];
    float s = xv.x * wv.x + xv.y * wv.y + xv.z * wv.z + xv.w * wv.w;
    #pragma unroll
    for (int off = 16; off > 0; off >>= 1)
        s += __shfl_xor_sync(0xFFFFFFFFu, s, off);
    if (lane == 0) g_xw[br][row] = s;
}

// Fused gather for both branches. Warp per row, float4 per lane.
// k-loop metadata lives in registers, broadcast via shfl (ALU pipe) so the
// L1tex pipe carries ONLY the irreducible gather wavefronts.
__global__ __launch_bounds__(256) void fused_gather_kernel(
    const float* __restrict__ x1, const int* __restrict__ idx1, const float* __restrict__ dm1,
    const float* __restrict__ x2, const int* __restrict__ idx2, const float* __restrict__ dm2,
    const float* __restrict__ b_out,
    float* __restrict__ op1, float* __restrict__ os1,
    float* __restrict__ op2, float* __restrict__ os2)
{
    const int br = blockIdx.y;
    const float* __restrict__ x   = br ? x2   : x1;
    const int*   __restrict__ idx = br ? idx2 : idx1;
    const float* __restrict__ dm  = br ? dm2  : dm1;
    float*       __restrict__ op  = br ? op2  : op1;
    float*       __restrict__ os  = br ? os2  : os1;
    const float* __restrict__ xw  = g_xw[br];

    const int warp = threadIdx.x >> 5;
    const int lane = threadIdx.x & 31;
    const int n    = blockIdx.x * 8 + warp;
    const unsigned FULL = 0xFFFFFFFFu;

    // Lane l owns the metadata for k == l.
    const int   a      = idx[n * K_ANCH + lane];   // coalesced
    const float d      = dm [n * K_ANCH + lane];   // coalesced
    const int   my_off = a * (int)(D_FEAT * sizeof(float));

    // op for this lane's k (4B gather from the 128KB xw table).
    const float opv = d * __ldg(&xw[a]) + b_out[0];

    const char* __restrict__ xb = reinterpret_cast<const char*>(x);
    const int lane_byte = lane * 16;

    float4 acc0 = make_float4(0.f, 0.f, 0.f, 0.f);
    float4 acc1 = make_float4(0.f, 0.f, 0.f, 0.f);

    #pragma unroll
    for (int k = 0; k < K_ANCH; k += 2) {
        int   o0 = __shfl_sync(FULL, my_off, k);
        float d0 = __shfl_sync(FULL, d,      k);
        int   o1 = __shfl_sync(FULL, my_off, k + 1);
        float d1 = __shfl_sync(FULL, d,      k + 1);
        float4 v0 = __ldg(reinterpret_cast<const float4*>(xb + o0 + lane_byte));
        float4 v1 = __ldg(reinterpret_cast<const float4*>(xb + o1 + lane_byte));
        acc0.x += d0 * v0.x; acc0.y += d0 * v0.y;
        acc0.z += d0 * v0.z; acc0.w += d0 * v0.w;
        acc1.x += d1 * v1.x; acc1.y += d1 * v1.y;
        acc1.z += d1 * v1.z; acc1.w += d1 * v1.w;
    }

    const float inv = 1.0f / (float)K_ANCH;
    float4 acc;
    acc.x = (acc0.x + acc1.x) * inv;
    acc.y = (acc0.y + acc1.y) * inv;
    acc.z = (acc0.z + acc1.z) * inv;
    acc.w = (acc0.w + acc1.w) * inv;

    reinterpret_cast<float4*>(os)[n * (D_FEAT / 4) + lane] = acc;   // coalesced
    op[n * K_ANCH + lane] = opv;                                    // coalesced
}

extern "C" void kernel_launch(void* const* d_in, const int* in_sizes, int n_in,
                              void* d_out, int out_size) {
    const float* x1   = (const float*)d_in[0];
    const int*   idx1 = (const int*)  d_in[1];
    const float* dm1  = (const float*)d_in[2];
    const float* x2   = (const float*)d_in[3];
    const int*   idx2 = (const int*)  d_in[4];
    const float* dm2  = (const float*)d_in[5];
    const float* w    = (const float*)d_in[6];
    const float* b    = (const float*)d_in[7];

    float* out = (float*)d_out;
    float* op1 = out;                                       // [N, K]
    float* os1 = op1 + (size_t)N_ROWS * K_ANCH;             // [N, D]
    float* op2 = os1 + (size_t)N_ROWS * D_FEAT;             // [N, K]
    float* os2 = op2 + (size_t)N_ROWS * K_ANCH;             // [N, D]

    dim3 xg(N_ROWS / 8, 2);
    xw_kernel<<<xg, 256>>>(x1, x2, w);

    dim3 gg(N_ROWS / 8, 2);
    fused_gather_kernel<<<gg, 256>>>(x1, idx1, dm1, x2, idx2, dm2, b,
                                     op1, os1, op2, os2);
}